// round 5
// baseline (speedup 1.0000x reference)
#include <cuda_runtime.h>
#include <cstdint>

#define D_MODEL   512
#define BATCH     128
#define NATOM     512
#define M_TOT     (BATCH * NATOM)
#define NEXP      8
#define NELEM     4
#define NCHG      3
#define NCOMBO    12

#define SLICES    24
#define TPB       256
#define WARPS_PB  (TPB / 32)

// ---------------- device scratch (no allocation allowed) ----------------
__device__ float g_wgT[NEXP * D_MODEL];          // Wg transposed: [x][d]
__device__ float g_gate[BATCH * NEXP];           // sum of softmax over atoms
__device__ float g_eo[BATCH * NEXP];             // sum of pe*|pc| over atoms
__device__ int   g_count[NCOMBO];
__device__ int   g_idx[NCOMBO][M_TOT];

// ---------------- packed f32x2 helpers ----------------
__device__ __forceinline__ void fma2(unsigned long long& d,
                                     unsigned long long a,
                                     unsigned long long b) {
    asm volatile("fma.rn.f32x2 %0, %1, %2, %0;" : "+l"(d) : "l"(a), "l"(b));
}
__device__ __forceinline__ float upk_sum(unsigned long long v) {
    float a, b;
    asm("mov.b64 {%0, %1}, %2;" : "=f"(a), "=f"(b) : "l"(v));
    return a + b;
}

// ---------------- prep: transpose Wg, zero accumulators ----------------
__global__ void prep_kernel(const float* __restrict__ Wg) {
    int i = blockIdx.x * blockDim.x + threadIdx.x;   // 0..4095
    if (i < NEXP * D_MODEL) {
        int x = i >> 9;          // expert
        int d = i & 511;
        g_wgT[x * D_MODEL + d] = Wg[d * NEXP + x];
    }
    if (i < BATCH * NEXP) {
        g_gate[i] = 0.0f;
        g_eo[i]   = 0.0f;
    }
    if (i < NCOMBO) g_count[i] = 0;
}

// ---------------- compaction: bucket atoms by (E,C) combo ----------------
__global__ void compact_kernel(const int* __restrict__ E,
                               const int* __restrict__ C) {
    int i = blockIdx.x * blockDim.x + threadIdx.x;   // exactly M_TOT threads
    int combo = E[i] * NCHG + C[i];
    unsigned mask = __match_any_sync(0xffffffffu, combo);
    int lane = threadIdx.x & 31;
    int leader = __ffs(mask) - 1;
    int base = 0;
    if (lane == leader) base = atomicAdd(&g_count[combo], __popc(mask));
    base = __shfl_sync(mask, base, leader);
    int rank = __popc(mask & ((1u << lane) - 1));
    g_idx[combo][base + rank] = i;
}

// ---------------- main: 24 dots per atom, 4 atoms per warp pass ----------------
// Lane layout: lane = g*8 + l ; g = atom slot (0..3), l = d-slice / expert id.
// Lane (g,l) covers d = 4*l + 32*s, s = 0..15 (64 floats = 16 float4 per atom).
// Weight reads broadcast across the 4 atom groups (same address), conflict-free
// within a group (8 lanes x float4 = 128B).
__device__ __forceinline__ float dot_row(const ulonglong2* xr,
                                         const float* wrow, int l) {
    const ulonglong2* wp = reinterpret_cast<const ulonglong2*>(wrow) + l;
    unsigned long long a0 = 0ull, a1 = 0ull;
#pragma unroll
    for (int s = 0; s < 16; s++) {
        ulonglong2 w = wp[s * 8];
        fma2(a0, xr[s].x, w.x);
        fma2(a1, xr[s].y, w.y);
    }
    float d = upk_sum(a0) + upk_sum(a1);
    d += __shfl_xor_sync(0xffffffffu, d, 1);
    d += __shfl_xor_sync(0xffffffffu, d, 2);
    d += __shfl_xor_sync(0xffffffffu, d, 4);
    return d;
}

__global__ __launch_bounds__(TPB)
void moe_main_kernel(const float* __restrict__ X,
                     const float* __restrict__ We,
                     const float* __restrict__ Wc,
                     const float* __restrict__ bg,
                     const float* __restrict__ be,
                     const float* __restrict__ bc) {
    __shared__ __align__(16) float sw[24 * D_MODEL];   // 48 KB exactly

    const int combo = blockIdx.y;
    const int El = combo / NCHG;
    const int Cl = combo - El * NCHG;
    const int tid = threadIdx.x;

    // Load weight tile: rows 0-7 gate, 8-15 We[x][El], 16-23 Wc[x][Cl]
    {
        const float4* wg4 = reinterpret_cast<const float4*>(g_wgT);
        float4* sw4 = reinterpret_cast<float4*>(sw);
#pragma unroll
        for (int i = tid; i < NEXP * (D_MODEL / 4); i += TPB)
            sw4[i] = wg4[i];
#pragma unroll
        for (int i = tid; i < NEXP * (D_MODEL / 4); i += TPB) {
            int x = i / (D_MODEL / 4);
            int c = i % (D_MODEL / 4);
            reinterpret_cast<float4*>(sw + (8 + x) * D_MODEL)[c] =
                reinterpret_cast<const float4*>(We + (size_t)(x * NELEM + El) * D_MODEL)[c];
            reinterpret_cast<float4*>(sw + (16 + x) * D_MODEL)[c] =
                reinterpret_cast<const float4*>(Wc + (size_t)(x * NCHG + Cl) * D_MODEL)[c];
        }
    }
    __syncthreads();

    const int L = g_count[combo];
    const int wid  = tid >> 5;
    const int lane = tid & 31;
    const int g = lane >> 3;
    const int l = lane & 7;
    const int* __restrict__ idxp = g_idx[combo];

    // per-expert biases (lane l owns expert l of its atom)
    const float bgl = __ldg(bg + l);
    const float bel = __ldg(be + l * NELEM + El);
    const float bcl = __ldg(bc + l * NCHG + Cl);

    for (int t = blockIdx.x * WARPS_PB + wid; t * 4 < L;
         t += gridDim.x * WARPS_PB) {
        const int i0 = t * 4;
        const int ai = i0 + g;
        const bool active = (ai < L);
        const int m = idxp[active ? ai : i0];

        // load this atom slot's X slice: 16 x 16B
        const ulonglong2* xp =
            reinterpret_cast<const ulonglong2*>(X + (size_t)m * D_MODEL) + l;
        ulonglong2 xr[16];
#pragma unroll
        for (int s = 0; s < 16; s++) xr[s] = xp[s * 8];

        float gl = 0.f, pev = 0.f, pcv = 0.f;
#pragma unroll
        for (int rr = 0; rr < 8; rr++) {
            float dv = dot_row(xr, sw + rr * D_MODEL, l);
            gl = (l == rr) ? dv : gl;
        }
#pragma unroll
        for (int rr = 0; rr < 8; rr++) {
            float dv = dot_row(xr, sw + (8 + rr) * D_MODEL, l);
            pev = (l == rr) ? dv : pev;
        }
#pragma unroll
        for (int rr = 0; rr < 8; rr++) {
            float dv = dot_row(xr, sw + (16 + rr) * D_MODEL, l);
            pcv = (l == rr) ? dv : pcv;
        }

        // epilogue: per-atom softmax over 8 experts (one per lane in group)
        gl += bgl;
        float mx = gl;
        mx = fmaxf(mx, __shfl_xor_sync(0xffffffffu, mx, 1));
        mx = fmaxf(mx, __shfl_xor_sync(0xffffffffu, mx, 2));
        mx = fmaxf(mx, __shfl_xor_sync(0xffffffffu, mx, 4));
        float e = __expf(gl - mx);
        float se = e;
        se += __shfl_xor_sync(0xffffffffu, se, 1);
        se += __shfl_xor_sync(0xffffffffu, se, 2);
        se += __shfl_xor_sync(0xffffffffu, se, 4);
        float gate = e / se;
        float term = (pev + bel) * fabsf(pcv + bcl);

        if (active) {
            int b = m >> 9;   // N = 512
            atomicAdd(&g_gate[b * NEXP + l], gate);
            atomicAdd(&g_eo[b * NEXP + l], term);
        }
    }
}

// ---------------- finalize: out[b] = -sum_x gate*eo ----------------
__global__ void finalize_kernel(float* __restrict__ out) {
    int b = threadIdx.x;
    if (b < BATCH) {
        float s = 0.f;
#pragma unroll
        for (int x = 0; x < NEXP; x++)
            s += g_gate[b * NEXP + x] * g_eo[b * NEXP + x];
        out[b] = -s;
    }
}

// ---------------- launch ----------------
extern "C" void kernel_launch(void* const* d_in, const int* in_sizes, int n_in,
                              void* d_out, int out_size) {
    const float* X  = (const float*)d_in[0];
    const int*   E  = (const int*)d_in[1];
    const int*   C  = (const int*)d_in[2];
    const float* Wg = (const float*)d_in[3];
    const float* bg = (const float*)d_in[4];
    const float* We = (const float*)d_in[5];
    const float* be = (const float*)d_in[6];
    const float* Wc = (const float*)d_in[7];
    const float* bc = (const float*)d_in[8];

    prep_kernel<<<16, 256>>>(Wg);
    compact_kernel<<<M_TOT / 256, 256>>>(E, C);
    moe_main_kernel<<<dim3(SLICES, NCOMBO), TPB>>>(X, We, Wc, bg, be, bc);
    finalize_kernel<<<1, 128>>>((float*)d_out);
}

// round 10
// speedup vs baseline: 1.1886x; 1.1886x over previous
#include <cuda_runtime.h>
#include <cstdint>

#define D_MODEL   512
#define BATCH     128
#define NATOM     512
#define M_TOT     (BATCH * NATOM)
#define NEXP      8
#define NELEM     4
#define NCHG      3
#define NCOMBO    12

#define SLICES    37          // grid.x of main kernel -> 444 blocks
#define TPB       128
#define WARPS_PB  (TPB / 32)

// row stride in 16-byte (ulonglong2 = 4 float) units: 512 floats / 4 = 128
#define ROW_U2    (D_MODEL / 4)

typedef unsigned long long ull;

// ---------------- device scratch (zero-initialized at module load; finalize
// re-zeros after each run so every kernel_launch call sees clean state) -----
__device__ float g_wgT[NEXP * D_MODEL];          // Wg transposed: [x][d]
__device__ float g_gate[BATCH * NEXP];
__device__ float g_eo[BATCH * NEXP];
__device__ int   g_count[NCOMBO];
__device__ int   g_idx[NCOMBO][M_TOT];

// ---------------- packed f32x2 helpers ----------------
__device__ __forceinline__ void fma2(ull& d, ull a, ull b) {
    asm volatile("fma.rn.f32x2 %0, %1, %2, %0;" : "+l"(d) : "l"(a), "l"(b));
}
__device__ __forceinline__ float upk_sum(ull v) {
    float a, b;
    asm("mov.b64 {%0, %1}, %2;" : "=f"(a), "=f"(b) : "l"(v));
    return a + b;
}

// ---------------- compaction + Wg transpose ----------------
__global__ void compact_kernel(const int* __restrict__ E,
                               const int* __restrict__ C,
                               const float* __restrict__ Wg) {
    int i = blockIdx.x * blockDim.x + threadIdx.x;   // exactly M_TOT threads
    int combo = E[i] * NCHG + C[i];
    unsigned mask = __match_any_sync(0xffffffffu, combo);
    int lane = threadIdx.x & 31;
    int leader = __ffs(mask) - 1;
    int base = 0;
    if (lane == leader) base = atomicAdd(&g_count[combo], __popc(mask));
    base = __shfl_sync(mask, base, leader);
    int rank = __popc(mask & ((1u << lane) - 1));
    g_idx[combo][base + rank] = i;

    // block 0 additionally transposes Wg (4096 elements)
    if (blockIdx.x == 0) {
        for (int j = threadIdx.x; j < NEXP * D_MODEL; j += blockDim.x) {
            int x = j >> 9;
            int d = j & 511;
            g_wgT[x * D_MODEL + d] = Wg[d * NEXP + x];
        }
    }
}

// ---------------- 7-shuffle tree reduce: 8 rows across 8 lanes -------------
// v[0..7] are per-lane partials of rows 0..7 (of one 8-lane group).
// Returns, in lane l (group-local id = lane&7), the full sum of row l.
__device__ __forceinline__ float reduce8(const float* v, int l) {
    const bool b0 = l & 1, b1 = l & 2, b2 = l & 4;
    float n0 = (b0 ? v[1] : v[0]) + __shfl_xor_sync(0xffffffffu, b0 ? v[0] : v[1], 1);
    float n1 = (b0 ? v[3] : v[2]) + __shfl_xor_sync(0xffffffffu, b0 ? v[2] : v[3], 1);
    float n2 = (b0 ? v[5] : v[4]) + __shfl_xor_sync(0xffffffffu, b0 ? v[4] : v[5], 1);
    float n3 = (b0 ? v[7] : v[6]) + __shfl_xor_sync(0xffffffffu, b0 ? v[6] : v[7], 1);
    float m0 = (b1 ? n1 : n0) + __shfl_xor_sync(0xffffffffu, b1 ? n0 : n1, 2);
    float m1 = (b1 ? n3 : n2) + __shfl_xor_sync(0xffffffffu, b1 ? n2 : n3, 2);
    return (b2 ? m1 : m0) + __shfl_xor_sync(0xffffffffu, b2 ? m0 : m1, 4);
}

// ---------------- main kernel ----------------
// Lane = g*8 + l. g = atom slot (0..3), l = expert id / d-slice.
// Each thread processes TWO atoms (slots g and g+4): every weight LDS.128
// (broadcast over the 4 g-groups) feeds 8 atoms.
// Transposed accumulation: 24 f32x2 accumulators per atom stay live across
// the d loop -> ~48 independent FMA chains, no exposed FFMA latency.
__global__ __launch_bounds__(TPB)
void moe_main_kernel(const float* __restrict__ X,
                     const float* __restrict__ We,
                     const float* __restrict__ Wc,
                     const float* __restrict__ bg,
                     const float* __restrict__ be,
                     const float* __restrict__ bc) {
    __shared__ __align__(16) float sw[24 * D_MODEL];   // 48 KB exactly

    const int combo = blockIdx.y;
    const int El = combo / NCHG;
    const int Cl = combo - El * NCHG;
    const int tid = threadIdx.x;

    // Load weight tile: rows 0-7 gate, 8-15 We[x][El], 16-23 Wc[x][Cl]
    {
        const float4* wg4 = reinterpret_cast<const float4*>(g_wgT);
        float4* sw4 = reinterpret_cast<float4*>(sw);
#pragma unroll
        for (int i = tid; i < NEXP * (D_MODEL / 4); i += TPB)
            sw4[i] = wg4[i];
#pragma unroll
        for (int i = tid; i < NEXP * (D_MODEL / 4); i += TPB) {
            int x = i / (D_MODEL / 4);
            int c = i % (D_MODEL / 4);
            reinterpret_cast<float4*>(sw + (8 + x) * D_MODEL)[c] =
                reinterpret_cast<const float4*>(We + (size_t)(x * NELEM + El) * D_MODEL)[c];
            reinterpret_cast<float4*>(sw + (16 + x) * D_MODEL)[c] =
                reinterpret_cast<const float4*>(Wc + (size_t)(x * NCHG + Cl) * D_MODEL)[c];
        }
    }
    __syncthreads();

    const int L = g_count[combo];
    const int wid  = tid >> 5;
    const int lane = tid & 31;
    const int g = lane >> 3;
    const int l = lane & 7;
    const int* __restrict__ idxp = g_idx[combo];

    // row r, slice s, lane l lives at ulonglong2 index r*ROW_U2 + s*8 + l
    const ulonglong2* __restrict__ swu =
        reinterpret_cast<const ulonglong2*>(sw) + l;

    const float bgl = __ldg(bg + l);
    const float bel = __ldg(be + l * NELEM + El);
    const float bcl = __ldg(bc + l * NCHG + Cl);

    for (int t = blockIdx.x * WARPS_PB + wid; t * 8 < L;
         t += gridDim.x * WARPS_PB) {
        const int i0 = t * 8;
        const int aA = i0 + g;
        const int aB = i0 + 4 + g;
        const bool actA = (aA < L);
        const bool actB = (aB < L);
        const int mA = idxp[actA ? aA : 0];
        const int mB = idxp[actB ? aB : 0];

        const ulonglong2* __restrict__ xpA =
            reinterpret_cast<const ulonglong2*>(X + (size_t)mA * D_MODEL) + l;
        const ulonglong2* __restrict__ xpB =
            reinterpret_cast<const ulonglong2*>(X + (size_t)mB * D_MODEL) + l;

        ull accA[24], accB[24];
#pragma unroll
        for (int r = 0; r < 24; r++) { accA[r] = 0ull; accB[r] = 0ull; }

        ulonglong2 xA = xpA[0], xB = xpB[0];
#pragma unroll
        for (int s = 0; s < 16; s++) {
            ulonglong2 nA, nB;
            if (s < 15) { nA = xpA[(s + 1) * 8]; nB = xpB[(s + 1) * 8]; }
            const ulonglong2* wp = swu + s * 8;
#pragma unroll
            for (int r = 0; r < 24; r++) {
                ulonglong2 w = wp[r * ROW_U2];     // FIXED: was r*64 (half stride)
                fma2(accA[r], xA.x, w.x);
                fma2(accA[r], xA.y, w.y);
                fma2(accB[r], xB.x, w.x);
                fma2(accB[r], xB.y, w.y);
            }
            if (s < 15) { xA = nA; xB = nB; }
        }

        float vA[24], vB[24];
#pragma unroll
        for (int r = 0; r < 24; r++) {
            vA[r] = upk_sum(accA[r]);
            vB[r] = upk_sum(accB[r]);
        }

        // lane l ends up holding expert-l values for its group's atoms
        float glA = reduce8(vA,      l) + bgl;
        float peA = reduce8(vA + 8,  l) + bel;
        float pcA = reduce8(vA + 16, l) + bcl;
        float glB = reduce8(vB,      l) + bgl;
        float peB = reduce8(vB + 8,  l) + bel;
        float pcB = reduce8(vB + 16, l) + bcl;

        // per-atom softmax over the 8 experts (butterfly within 8-lane group)
        float mxA = glA, mxB = glB;
#pragma unroll
        for (int k = 1; k <= 4; k <<= 1) {
            mxA = fmaxf(mxA, __shfl_xor_sync(0xffffffffu, mxA, k));
            mxB = fmaxf(mxB, __shfl_xor_sync(0xffffffffu, mxB, k));
        }
        float eA = __expf(glA - mxA);
        float eB = __expf(glB - mxB);
        float sA = eA, sB = eB;
#pragma unroll
        for (int k = 1; k <= 4; k <<= 1) {
            sA += __shfl_xor_sync(0xffffffffu, sA, k);
            sB += __shfl_xor_sync(0xffffffffu, sB, k);
        }
        float gateA = eA / sA;
        float gateB = eB / sB;
        float termA = peA * fabsf(pcA);
        float termB = peB * fabsf(pcB);

        if (actA) {
            int b = mA >> 9;
            atomicAdd(&g_gate[b * NEXP + l], gateA);
            atomicAdd(&g_eo[b * NEXP + l], termA);
        }
        if (actB) {
            int b = mB >> 9;
            atomicAdd(&g_gate[b * NEXP + l], gateB);
            atomicAdd(&g_eo[b * NEXP + l], termB);
        }
    }
}

// ---------------- finalize: output + scratch cleanup for next run ----------
__global__ void finalize_kernel(float* __restrict__ out) {
    int b = threadIdx.x;
    if (b < BATCH) {
        float s = 0.f;
#pragma unroll
        for (int x = 0; x < NEXP; x++)
            s += g_gate[b * NEXP + x] * g_eo[b * NEXP + x];
        out[b] = -s;
#pragma unroll
        for (int x = 0; x < NEXP; x++) {
            g_gate[b * NEXP + x] = 0.f;
            g_eo[b * NEXP + x]   = 0.f;
        }
    }
    if (b < NCOMBO) g_count[b] = 0;
}

// ---------------- launch ----------------
extern "C" void kernel_launch(void* const* d_in, const int* in_sizes, int n_in,
                              void* d_out, int out_size) {
    const float* X  = (const float*)d_in[0];
    const int*   E  = (const int*)d_in[1];
    const int*   C  = (const int*)d_in[2];
    const float* Wg = (const float*)d_in[3];
    const float* bg = (const float*)d_in[4];
    const float* We = (const float*)d_in[5];
    const float* be = (const float*)d_in[6];
    const float* Wc = (const float*)d_in[7];
    const float* bc = (const float*)d_in[8];

    compact_kernel<<<M_TOT / 256, 256>>>(E, C, Wg);
    moe_main_kernel<<<dim3(SLICES, NCOMBO), TPB>>>(X, We, Wc, bg, be, bc);
    finalize_kernel<<<1, 128>>>((float*)d_out);
}

// round 13
// speedup vs baseline: 1.5464x; 1.3010x over previous
#include <cuda_runtime.h>
#include <cstdint>

#define D_MODEL   512
#define BATCH     128
#define NATOM     512
#define M_TOT     (BATCH * NATOM)
#define NEXP      8
#define NELEM     4
#define NCHG      3
#define NCOMBO    12

#define SLICES    24          // grid.x -> 288 blocks = one wave at 2 blocks/SM
#define TPB       128
#define WARPS_PB  (TPB / 32)
#define NBLOCKS   (SLICES * NCOMBO)

// row stride in 16-byte (ulonglong2 = 4 float) units: 512 floats / 4 = 128
#define ROW_U2    (D_MODEL / 4)

typedef unsigned long long ull;

// ---------------- device scratch (zero-initialized at module load; the last
// main-kernel block re-zeros everything so each replay sees clean state) ----
__device__ float g_wgT[NEXP * D_MODEL];          // Wg transposed: [x][d]
__device__ float g_gate[BATCH * NEXP];
__device__ float g_eo[BATCH * NEXP];
__device__ int   g_count[NCOMBO];
__device__ int   g_done;
__device__ int   g_idx[NCOMBO][M_TOT];

// ---------------- packed f32x2 helpers (NOT volatile: let ptxas schedule) --
__device__ __forceinline__ void fma2(ull& d, ull a, ull b) {
    asm("fma.rn.f32x2 %0, %1, %2, %0;" : "+l"(d) : "l"(a), "l"(b));
}
__device__ __forceinline__ float upk_sum(ull v) {
    float a, b;
    asm("mov.b64 {%0, %1}, %2;" : "=f"(a), "=f"(b) : "l"(v));
    return a + b;
}

// ---------------- compaction + Wg transpose ----------------
__global__ void compact_kernel(const int* __restrict__ E,
                               const int* __restrict__ C,
                               const float* __restrict__ Wg) {
    int i = blockIdx.x * blockDim.x + threadIdx.x;   // exactly M_TOT threads
    int combo = E[i] * NCHG + C[i];
    unsigned mask = __match_any_sync(0xffffffffu, combo);
    int lane = threadIdx.x & 31;
    int leader = __ffs(mask) - 1;
    int base = 0;
    if (lane == leader) base = atomicAdd(&g_count[combo], __popc(mask));
    base = __shfl_sync(mask, base, leader);
    int rank = __popc(mask & ((1u << lane) - 1));
    g_idx[combo][base + rank] = i;

    if (blockIdx.x == 0) {
        for (int j = threadIdx.x; j < NEXP * D_MODEL; j += blockDim.x) {
            int x = j >> 9;
            int d = j & 511;
            g_wgT[x * D_MODEL + d] = Wg[d * NEXP + x];
        }
    }
}

// ---------------- 7-shuffle tree reduce: 8 rows across 8 lanes -------------
__device__ __forceinline__ float reduce8(const float* v, int l) {
    const bool b0 = l & 1, b1 = l & 2, b2 = l & 4;
    float n0 = (b0 ? v[1] : v[0]) + __shfl_xor_sync(0xffffffffu, b0 ? v[0] : v[1], 1);
    float n1 = (b0 ? v[3] : v[2]) + __shfl_xor_sync(0xffffffffu, b0 ? v[2] : v[3], 1);
    float n2 = (b0 ? v[5] : v[4]) + __shfl_xor_sync(0xffffffffu, b0 ? v[4] : v[5], 1);
    float n3 = (b0 ? v[7] : v[6]) + __shfl_xor_sync(0xffffffffu, b0 ? v[6] : v[7], 1);
    float m0 = (b1 ? n1 : n0) + __shfl_xor_sync(0xffffffffu, b1 ? n0 : n1, 2);
    float m1 = (b1 ? n3 : n2) + __shfl_xor_sync(0xffffffffu, b1 ? n2 : n3, 2);
    return (b2 ? m1 : m0) + __shfl_xor_sync(0xffffffffu, b2 ? m0 : m1, 4);
}

// ---------------- main kernel (fused finalize) ----------------
// Lane = g*8 + l. g = atom slot (0..3), l = expert id / d-slice.
// 2 atoms per thread; 24 f32x2 accumulators live across the d loop.
// X is streamed with a distance-4 rotating prefetch, software-pipelined
// ACROSS passes: slices 0..3 of the next pass are issued during slices
// 12..15 of the current pass, and next-pass idx loads are issued at pass top.
__global__ __launch_bounds__(TPB, 2)
void moe_main_kernel(const float* __restrict__ X,
                     const float* __restrict__ We,
                     const float* __restrict__ Wc,
                     const float* __restrict__ bg,
                     const float* __restrict__ be,
                     const float* __restrict__ bc,
                     float* __restrict__ out) {
    __shared__ __align__(16) float sw[24 * D_MODEL];   // 48 KB exactly
    __shared__ int s_last;

    const int combo = blockIdx.y;
    const int El = combo / NCHG;
    const int Cl = combo - El * NCHG;
    const int tid = threadIdx.x;

    // Load weight tile: rows 0-7 gate, 8-15 We[x][El], 16-23 Wc[x][Cl]
    {
        const float4* wg4 = reinterpret_cast<const float4*>(g_wgT);
        float4* sw4 = reinterpret_cast<float4*>(sw);
#pragma unroll
        for (int i = tid; i < NEXP * (D_MODEL / 4); i += TPB)
            sw4[i] = wg4[i];
#pragma unroll
        for (int i = tid; i < NEXP * (D_MODEL / 4); i += TPB) {
            int x = i / (D_MODEL / 4);
            int c = i % (D_MODEL / 4);
            reinterpret_cast<float4*>(sw + (8 + x) * D_MODEL)[c] =
                reinterpret_cast<const float4*>(We + (size_t)(x * NELEM + El) * D_MODEL)[c];
            reinterpret_cast<float4*>(sw + (16 + x) * D_MODEL)[c] =
                reinterpret_cast<const float4*>(Wc + (size_t)(x * NCHG + Cl) * D_MODEL)[c];
        }
    }
    __syncthreads();

    const int L = g_count[combo];
    const int wid  = tid >> 5;
    const int lane = tid & 31;
    const int g = lane >> 3;
    const int l = lane & 7;
    const int* __restrict__ idxp = g_idx[combo];
    const int stride = SLICES * WARPS_PB;

    // row r, slice s, lane l lives at ulonglong2 index r*ROW_U2 + s*8 + l
    const ulonglong2* __restrict__ swu =
        reinterpret_cast<const ulonglong2*>(sw) + l;

    const float bgl = __ldg(bg + l);
    const float bel = __ldg(be + l * NELEM + El);
    const float bcl = __ldg(bc + l * NCHG + Cl);

    int t = blockIdx.x * WARPS_PB + wid;
    if (t * 8 < L) {
        // ---- prologue: current indices + first 4 slices in flight ----
        int aA = t * 8 + g, aB = t * 8 + 4 + g;
        bool actA = (aA < L), actB = (aB < L);
        int mA = idxp[actA ? aA : 0];
        int mB = idxp[actB ? aB : 0];
        const ulonglong2* xpA =
            reinterpret_cast<const ulonglong2*>(X + (size_t)mA * D_MODEL) + l;
        const ulonglong2* xpB =
            reinterpret_cast<const ulonglong2*>(X + (size_t)mB * D_MODEL) + l;

        ulonglong2 bufA[4], bufB[4];
#pragma unroll
        for (int s = 0; s < 4; s++) { bufA[s] = xpA[s * 8]; bufB[s] = xpB[s * 8]; }

        while (true) {
            // ---- prefetch next pass's indices (consumed at slice 12) ----
            const int tn = t + stride;
            const bool hasn = (tn * 8 < L);
            const int aAn = tn * 8 + g, aBn = tn * 8 + 4 + g;
            const bool actAn = hasn && (aAn < L);
            const bool actBn = hasn && (aBn < L);
            const int mAn = idxp[actAn ? aAn : 0];
            const int mBn = idxp[actBn ? aBn : 0];
            const ulonglong2* xpAn =
                reinterpret_cast<const ulonglong2*>(X + (size_t)mAn * D_MODEL) + l;
            const ulonglong2* xpBn =
                reinterpret_cast<const ulonglong2*>(X + (size_t)mBn * D_MODEL) + l;

            ull accA[24], accB[24];
#pragma unroll
            for (int r = 0; r < 24; r++) { accA[r] = 0ull; accB[r] = 0ull; }

#pragma unroll
            for (int s = 0; s < 16; s++) {
                const ulonglong2 xA = bufA[s & 3], xB = bufB[s & 3];
                if (s < 12) {                     // refill for this pass
                    bufA[s & 3] = xpA[(s + 4) * 8];
                    bufB[s & 3] = xpB[(s + 4) * 8];
                } else {                          // preload next pass s-12
                    bufA[s & 3] = xpAn[(s - 12) * 8];
                    bufB[s & 3] = xpBn[(s - 12) * 8];
                }
                const ulonglong2* wp = swu + s * 8;
#pragma unroll
                for (int r = 0; r < 24; r++) {
                    ulonglong2 w = wp[r * ROW_U2];
                    fma2(accA[r], xA.x, w.x);
                    fma2(accA[r], xA.y, w.y);
                    fma2(accB[r], xB.x, w.x);
                    fma2(accB[r], xB.y, w.y);
                }
            }

            // ---- epilogue for current pass ----
            float vA[24], vB[24];
#pragma unroll
            for (int r = 0; r < 24; r++) {
                vA[r] = upk_sum(accA[r]);
                vB[r] = upk_sum(accB[r]);
            }

            float glA = reduce8(vA,      l) + bgl;
            float peA = reduce8(vA + 8,  l) + bel;
            float pcA = reduce8(vA + 16, l) + bcl;
            float glB = reduce8(vB,      l) + bgl;
            float peB = reduce8(vB + 8,  l) + bel;
            float pcB = reduce8(vB + 16, l) + bcl;

            float mxA = glA, mxB = glB;
#pragma unroll
            for (int k = 1; k <= 4; k <<= 1) {
                mxA = fmaxf(mxA, __shfl_xor_sync(0xffffffffu, mxA, k));
                mxB = fmaxf(mxB, __shfl_xor_sync(0xffffffffu, mxB, k));
            }
            float eA = __expf(glA - mxA);
            float eB = __expf(glB - mxB);
            float sA = eA, sB = eB;
#pragma unroll
            for (int k = 1; k <= 4; k <<= 1) {
                sA += __shfl_xor_sync(0xffffffffu, sA, k);
                sB += __shfl_xor_sync(0xffffffffu, sB, k);
            }
            if (actA) {
                int b = mA >> 9;
                atomicAdd(&g_gate[b * NEXP + l], eA / sA);
                atomicAdd(&g_eo[b * NEXP + l], peA * fabsf(pcA));
            }
            if (actB) {
                int b = mB >> 9;
                atomicAdd(&g_gate[b * NEXP + l], eB / sB);
                atomicAdd(&g_eo[b * NEXP + l], peB * fabsf(pcB));
            }

            if (!hasn) break;
            // ---- rotate pipeline state ----
            t = tn;
            mA = mAn; mB = mBn; actA = actAn; actB = actBn;
            xpA = xpAn; xpB = xpBn;
        }
    }

    // ---- fused finalize: last block to finish computes output + cleanup ----
    __threadfence();
    if (tid == 0) {
        int n = atomicAdd(&g_done, 1);
        s_last = (n == NBLOCKS - 1) ? 1 : 0;
    }
    __syncthreads();
    if (s_last) {
        int b = tid;               // TPB == BATCH == 128
        float s = 0.f;
#pragma unroll
        for (int x = 0; x < NEXP; x++)
            s += __ldcg(&g_gate[b * NEXP + x]) * __ldcg(&g_eo[b * NEXP + x]);
        out[b] = -s;
#pragma unroll
        for (int x = 0; x < NEXP; x++) {
            g_gate[b * NEXP + x] = 0.f;
            g_eo[b * NEXP + x]   = 0.f;
        }
        if (tid < NCOMBO) g_count[tid] = 0;
        if (tid == 0) g_done = 0;
    }
}

// ---------------- launch ----------------
extern "C" void kernel_launch(void* const* d_in, const int* in_sizes, int n_in,
                              void* d_out, int out_size) {
    const float* X  = (const float*)d_in[0];
    const int*   E  = (const int*)d_in[1];
    const int*   C  = (const int*)d_in[2];
    const float* Wg = (const float*)d_in[3];
    const float* bg = (const float*)d_in[4];
    const float* We = (const float*)d_in[5];
    const float* be = (const float*)d_in[6];
    const float* Wc = (const float*)d_in[7];
    const float* bc = (const float*)d_in[8];

    compact_kernel<<<M_TOT / 256, 256>>>(E, C, Wg);
    moe_main_kernel<<<dim3(SLICES, NCOMBO), TPB>>>(X, We, Wc, bg, be, bc,
                                                   (float*)d_out);
}

// round 14
// speedup vs baseline: 1.8653x; 1.2062x over previous
#include <cuda_runtime.h>
#include <cstdint>

#define D_MODEL   512
#define BATCH     128
#define NATOM     512
#define M_TOT     (BATCH * NATOM)
#define NEXP      8
#define NELEM     4
#define NCHG      3
#define NCOMBO    12

#define SLICES    37          // grid.x -> 444 blocks = one wave at 3 blocks/SM
#define TPB       128
#define WARPS_PB  (TPB / 32)
#define NBLOCKS   (SLICES * NCOMBO)

typedef unsigned long long ull;

// ---------------- device scratch (zero-initialized at module load; the last
// main-kernel block re-zeros everything so each replay sees clean state) ----
__device__ float g_wgT[NEXP * D_MODEL];          // Wg transposed: [x][d]
__device__ float g_gate[BATCH * NEXP];
__device__ float g_eo[BATCH * NEXP];
__device__ int   g_count[NCOMBO];
__device__ int   g_done;
__device__ int   g_idx[NCOMBO][M_TOT];

// ---------------- packed f32x2 helpers ----------------
__device__ __forceinline__ void fma2(ull& d, ull a, ull b) {
    asm("fma.rn.f32x2 %0, %1, %2, %0;" : "+l"(d) : "l"(a), "l"(b));
}
__device__ __forceinline__ float upk_sum(ull v) {
    float a, b;
    asm("mov.b64 {%0, %1}, %2;" : "=f"(a), "=f"(b) : "l"(v));
    return a + b;
}

// ---------------- compaction (block-aggregated) + Wg transpose -------------
__global__ void compact_kernel(const int* __restrict__ E,
                               const int* __restrict__ C,
                               const float* __restrict__ Wg) {
    __shared__ int scnt[NCOMBO];
    __shared__ int sbase[NCOMBO];
    const int tid = threadIdx.x;
    const int i = blockIdx.x * blockDim.x + tid;     // exactly M_TOT threads
    if (tid < NCOMBO) scnt[tid] = 0;
    __syncthreads();

    const int combo = E[i] * NCHG + C[i];
    unsigned mask = __match_any_sync(0xffffffffu, combo);
    const int lane = tid & 31;
    const int leader = __ffs(mask) - 1;
    int wbase = 0;
    if (lane == leader) wbase = atomicAdd(&scnt[combo], __popc(mask));
    wbase = __shfl_sync(mask, wbase, leader);
    const int pos = wbase + __popc(mask & ((1u << lane) - 1));
    __syncthreads();

    if (tid < NCOMBO) sbase[tid] = atomicAdd(&g_count[tid], scnt[tid]);
    __syncthreads();
    g_idx[combo][sbase[combo] + pos] = i;

    if (blockIdx.x == 0) {
        for (int j = tid; j < NEXP * D_MODEL; j += blockDim.x) {
            int x = j >> 9;
            int d = j & 511;
            g_wgT[x * D_MODEL + d] = Wg[d * NEXP + x];
        }
    }
}

// ---------------- 7-shuffle tree reduce across the 8 intra-octet lanes -----
// v[0..7] per-lane partials of 8 flat slots; lane l (= lane&7) gets slot l.
__device__ __forceinline__ float reduce8(const float* v, int l) {
    const bool b0 = l & 1, b1 = l & 2, b2 = l & 4;
    float n0 = (b0 ? v[1] : v[0]) + __shfl_xor_sync(0xffffffffu, b0 ? v[0] : v[1], 1);
    float n1 = (b0 ? v[3] : v[2]) + __shfl_xor_sync(0xffffffffu, b0 ? v[2] : v[3], 1);
    float n2 = (b0 ? v[5] : v[4]) + __shfl_xor_sync(0xffffffffu, b0 ? v[4] : v[5], 1);
    float n3 = (b0 ? v[7] : v[6]) + __shfl_xor_sync(0xffffffffu, b0 ? v[6] : v[7], 1);
    float m0 = (b1 ? n1 : n0) + __shfl_xor_sync(0xffffffffu, b1 ? n0 : n1, 2);
    float m1 = (b1 ? n3 : n2) + __shfl_xor_sync(0xffffffffu, b1 ? n2 : n3, 2);
    return (b2 ? m1 : m0) + __shfl_xor_sync(0xffffffffu, b2 ? m0 : m1, 4);
}

// ---------------- main kernel (fused finalize) ----------------
// Lane = g*8 + l: g = ROW-CLASS (rows rg*4+g) and LDS phase-octet,
//                 l = d-subchunk (16B of a 128B slice).
// One weight LDS.128 reads 4 DIFFERENT rows x 32 floats = 512 distinct bytes
// in 4 conflict-free phases (full smem bandwidth; the old layout wasted 4x on
// octet-duplicated broadcasts).
// A warp-pass covers 4 atoms; every lane accumulates acc[6 row-classes][4
// atoms] f32x2 partials over its 4-float d-chunks; X streams via a 3-deep
// rotating buffer of 4-atom 16B chunks.
__global__ __launch_bounds__(TPB, 3)
void moe_main_kernel(const float* __restrict__ X,
                     const float* __restrict__ We,
                     const float* __restrict__ Wc,
                     const float* __restrict__ bg,
                     const float* __restrict__ be,
                     const float* __restrict__ bc,
                     float* __restrict__ out) {
    __shared__ __align__(16) float sw[24 * D_MODEL];   // 48 KB
    __shared__ int s_last;

    const int combo = blockIdx.y;
    const int El = combo / NCHG;
    const int Cl = combo - El * NCHG;
    const int tid = threadIdx.x;

    // Weight tile: rows 0-7 gate (g_wgT), 8-15 We[x][El], 16-23 Wc[x][Cl]
    {
        const float4* wg4 = reinterpret_cast<const float4*>(g_wgT);
        float4* sw4 = reinterpret_cast<float4*>(sw);
#pragma unroll
        for (int i = tid; i < NEXP * (D_MODEL / 4); i += TPB)
            sw4[i] = wg4[i];
#pragma unroll
        for (int i = tid; i < NEXP * (D_MODEL / 4); i += TPB) {
            int x = i / (D_MODEL / 4);
            int c = i % (D_MODEL / 4);
            reinterpret_cast<float4*>(sw + (8 + x) * D_MODEL)[c] =
                reinterpret_cast<const float4*>(We + (size_t)(x * NELEM + El) * D_MODEL)[c];
            reinterpret_cast<float4*>(sw + (16 + x) * D_MODEL)[c] =
                reinterpret_cast<const float4*>(Wc + (size_t)(x * NCHG + Cl) * D_MODEL)[c];
        }
    }
    __syncthreads();

    const int L = g_count[combo];
    const int wid  = tid >> 5;
    const int lane = tid & 31;
    const int g = lane >> 3;          // row-class / LDS phase octet
    const int l = lane & 7;           // d-subchunk within a 128B slice
    const int a_mine = l & 3;         // atom this lane reports in epilogue
    const int x_mine = ((l >> 2) << 2) + g;   // expert this lane reports
    const int* __restrict__ idxp = g_idx[combo];
    const int warps_tot = SLICES * WARPS_PB;  // 148

    // per-lane weight base: w(rg, s) at swl[rg*512 + s*8] (ulonglong2 units)
    const ulonglong2* __restrict__ swl =
        reinterpret_cast<const ulonglong2*>(sw) + g * 128 + l;

    const float bgx = __ldg(bg + x_mine);
    const float bex = __ldg(be + x_mine * NELEM + El);
    const float bcx = __ldg(bc + x_mine * NCHG + Cl);

    for (int t = blockIdx.x * WARPS_PB + wid; t * 4 < L; t += warps_tot) {
        const int i0 = t * 4;
        int  m[4];
        bool act[4];
#pragma unroll
        for (int a = 0; a < 4; a++) {
            act[a] = (i0 + a < L);
            m[a] = idxp[act[a] ? i0 + a : 0];
        }
        const ulonglong2* xp[4];
#pragma unroll
        for (int a = 0; a < 4; a++)
            xp[a] = reinterpret_cast<const ulonglong2*>(X + (size_t)m[a] * D_MODEL) + l;
        // NOTE: lane offset within slice s is s*8 + l (ulonglong2 units);
        // all 4 octets read the same 16B -> 1 coalesced line per LDG.

        ull acc[6][4];
#pragma unroll
        for (int rg = 0; rg < 6; rg++)
#pragma unroll
            for (int a = 0; a < 4; a++) acc[rg][a] = 0ull;

        // 3-deep rotating X buffer (prefetch distance 3)
        ulonglong2 xb[3][4];
#pragma unroll
        for (int s = 0; s < 3; s++)
#pragma unroll
            for (int a = 0; a < 4; a++) xb[s][a] = xp[a][s * 8];

#pragma unroll
        for (int s = 0; s < 16; s++) {
            const int slot = s % 3;
#pragma unroll
            for (int rg = 0; rg < 6; rg++) {
                const ulonglong2 w = swl[rg * 512 + s * 8];
#pragma unroll
                for (int a = 0; a < 4; a++) {
                    fma2(acc[rg][a], xb[slot][a].x, w.x);
                    fma2(acc[rg][a], xb[slot][a].y, w.y);
                }
            }
            if (s + 3 < 16) {
#pragma unroll
                for (int a = 0; a < 4; a++) xb[slot][a] = xp[a][(s + 3) * 8];
            }
        }

        // ---- epilogue ----
        // flat slot f = (rg_local<<2) | a ; groups: gate rg 0-1, pe 2-3, pc 4-5
        float vg[8], vp[8], vc[8];
#pragma unroll
        for (int f = 0; f < 8; f++) {
            vg[f] = upk_sum(acc[(f >> 2)][f & 3]);
            vp[f] = upk_sum(acc[2 + (f >> 2)][f & 3]);
            vc[f] = upk_sum(acc[4 + (f >> 2)][f & 3]);
        }
        // after reduce8: lane (g,l) holds, for atom a_mine, expert x_mine:
        //   row x_mine (gate), row 8+x_mine (pe), row 16+x_mine (pc)
        float gl = reduce8(vg, l) + bgx;
        float pe = reduce8(vp, l) + bex;
        float pc = reduce8(vc, l) + bcx;

        // softmax over the 8 experts of atom a_mine: its lanes differ by
        // xor 4 (l bit2) and xor 8,16 (g bits)
        float mx = gl;
#pragma unroll
        for (int k = 4; k <= 16; k <<= 1)
            mx = fmaxf(mx, __shfl_xor_sync(0xffffffffu, mx, k));
        float e = __expf(gl - mx);
        float se = e;
#pragma unroll
        for (int k = 4; k <= 16; k <<= 1)
            se += __shfl_xor_sync(0xffffffffu, se, k);
        const float gate = e / se;
        const float term = pe * fabsf(pc);

        // lane's atom: select m/act by a_mine
        const int  msel  = (a_mine & 2) ? ((a_mine & 1) ? m[3] : m[2])
                                        : ((a_mine & 1) ? m[1] : m[0]);
        const bool asel  = (a_mine & 2) ? ((a_mine & 1) ? act[3] : act[2])
                                        : ((a_mine & 1) ? act[1] : act[0]);
        if (asel) {
            const int b = msel >> 9;                 // N = 512
            atomicAdd(&g_gate[b * NEXP + x_mine], gate);
            atomicAdd(&g_eo[b * NEXP + x_mine], term);
        }
    }

    // ---- fused finalize: last block computes output + cleans scratch ----
    __threadfence();
    if (tid == 0) {
        int n = atomicAdd(&g_done, 1);
        s_last = (n == NBLOCKS - 1) ? 1 : 0;
    }
    __syncthreads();
    if (s_last) {
        int b = tid;               // TPB == BATCH == 128
        float s = 0.f;
#pragma unroll
        for (int x = 0; x < NEXP; x++)
            s += __ldcg(&g_gate[b * NEXP + x]) * __ldcg(&g_eo[b * NEXP + x]);
        out[b] = -s;
#pragma unroll
        for (int x = 0; x < NEXP; x++) {
            g_gate[b * NEXP + x] = 0.f;
            g_eo[b * NEXP + x]   = 0.f;
        }
        if (tid < NCOMBO) g_count[tid] = 0;
        if (tid == 0) g_done = 0;
    }
}

// ---------------- launch ----------------
extern "C" void kernel_launch(void* const* d_in, const int* in_sizes, int n_in,
                              void* d_out, int out_size) {
    const float* X  = (const float*)d_in[0];
    const int*   E  = (const int*)d_in[1];
    const int*   C  = (const int*)d_in[2];
    const float* Wg = (const float*)d_in[3];
    const float* bg = (const float*)d_in[4];
    const float* We = (const float*)d_in[5];
    const float* be = (const float*)d_in[6];
    const float* Wc = (const float*)d_in[7];
    const float* bc = (const float*)d_in[8];

    compact_kernel<<<M_TOT / 256, 256>>>(E, C, Wg);
    moe_main_kernel<<<dim3(SLICES, NCOMBO), TPB>>>(X, We, Wc, bg, be, bc,
                                                   (float*)d_out);
}